// round 12
// baseline (speedup 1.0000x reference)
#include <cuda_runtime.h>
#include <cuda_fp16.h>
#include <cstdint>

// ---------------- problem constants ----------------
#define N_TOK   16384
#define DIM     1024
#define HEADS   8
#define DHEAD   64
#define HD      (HEADS * DHEAD)   // 512
#define QKVW    (3 * HD)          // 1536
#define WSZ     128
#define NWIN    (N_TOK / WSZ)     // 128

// ---------------- scratch ----------------
__device__ __half g_xh[(size_t)N_TOK * DIM];      // x -> half
__device__ __half g_wqkvT[(size_t)QKVW * DIM];    // w_qkv^T half  [1536][1024]
__device__ __half g_woutT[(size_t)DIM * HD];      // w_out^T half  [1024][512]
__device__ __half g_qkvh[(size_t)N_TOK * QKVW];   // GEMM1 out half
__device__ __half g_attnh[(size_t)N_TOK * HD];    // attention out half
__device__ __align__(16) __half g_zero16[8];      // 16B of zeros, 16B-aligned (cp.async src)

// ---------------- helpers ----------------
__device__ __forceinline__ unsigned h2u(__half2 h) {
    return *reinterpret_cast<unsigned*>(&h);
}

__device__ __forceinline__ void mma_f16(float c[4], unsigned a0, unsigned a1,
                                        unsigned a2, unsigned a3,
                                        unsigned b0, unsigned b1) {
    asm volatile(
        "mma.sync.aligned.m16n8k16.row.col.f32.f16.f16.f32 "
        "{%0,%1,%2,%3}, {%4,%5,%6,%7}, {%8,%9}, {%0,%1,%2,%3};"
        : "+f"(c[0]), "+f"(c[1]), "+f"(c[2]), "+f"(c[3])
        : "r"(a0), "r"(a1), "r"(a2), "r"(a3), "r"(b0), "r"(b1));
}

__device__ __forceinline__ void ldsm4(unsigned& r0, unsigned& r1,
                                      unsigned& r2, unsigned& r3, unsigned addr) {
    asm volatile("ldmatrix.sync.aligned.m8n8.x4.shared.b16 {%0,%1,%2,%3}, [%4];"
                 : "=r"(r0), "=r"(r1), "=r"(r2), "=r"(r3) : "r"(addr));
}

__device__ __forceinline__ void ldsm4t(unsigned& r0, unsigned& r1,
                                       unsigned& r2, unsigned& r3, unsigned addr) {
    asm volatile("ldmatrix.sync.aligned.m8n8.x4.trans.shared.b16 {%0,%1,%2,%3}, [%4];"
                 : "=r"(r0), "=r"(r1), "=r"(r2), "=r"(r3) : "r"(addr));
}

__global__ void cvt_f2h(const float4* __restrict__ in,
                        __half2* __restrict__ out, int n4)
{
    int i = blockIdx.x * blockDim.x + threadIdx.x;
    if (i < n4) {
        float4 v = in[i];
        out[2 * i + 0] = __floats2half2_rn(v.x, v.y);
        out[2 * i + 1] = __floats2half2_rn(v.z, v.w);
    }
}

// in[R][C] fp32 -> out[C][R] half. block (32,8), grid (C/32, R/32).
__global__ void transpose_f2h(const float* __restrict__ in,
                              __half* __restrict__ out, int R, int C)
{
    __shared__ float t[32][33];
    int bx = blockIdx.x * 32, by = blockIdx.y * 32;
    int x = bx + threadIdx.x;
#pragma unroll
    for (int i = 0; i < 32; i += 8) {
        int y = by + threadIdx.y + i;
        t[threadIdx.y + i][threadIdx.x] = in[(size_t)y * C + x];
    }
    __syncthreads();
    int xo = by + threadIdx.x;
#pragma unroll
    for (int i = 0; i < 32; i += 8) {
        int yo = bx + threadIdx.y + i;
        out[(size_t)yo * R + xo] = __float2half_rn(t[threadIdx.x][threadIdx.y + i]);
    }
}

// ---------------- FP16 tensor-core GEMM ----------------
// C[M,N] = A[M,K] @ Bt[N,K]^T (+bias). A, Bt half row-major.
// CTA 128x128x64(halves), 8 warps 2x4 (warp tile 64x32),
// 2-stage cp.async pipeline with ONE __syncthreads per k-tile,
// ldmatrix.x4 fragment loads. smem row r = 64 halves, 16B chunk c at c^(r&7).
// Stage layout (bytes): stage s base = s*32768; A [base, base+16384), B [base+16384, base+32768).
#define CPA16(dst, src) \
    asm volatile("cp.async.cg.shared.global [%0], [%1], 16;" :: "r"(dst), "l"(src))

#define HSTAGE 16384                       // halves per stage (A 8192 + B 8192)
#define HG_SMEM (2 * HSTAGE * 2)           // 65536 bytes

template <bool WITH_BIAS, bool HALF_OUT>
__global__ __launch_bounds__(256, 2)
void h16gemm(const __half* __restrict__ A, const __half* __restrict__ Bt,
             const float* __restrict__ bias, void* __restrict__ Cout,
             int M, int N, int K)
{
    extern __shared__ __half hsm[];
    const unsigned smBase = (unsigned)__cvta_generic_to_shared(hsm);

    const int tid  = threadIdx.x;
    const int lane = tid & 31;
    const int wid  = tid >> 5;
    const int wm   = wid >> 2;          // 0..1
    const int wn   = wid & 3;           // 0..3
    const int g    = lane >> 2;         // 0..7
    const int tg   = lane & 3;          // 0..3

    const int row0 = blockIdx.y * 128;
    const int col0 = blockIdx.x * 128;
    const int NKT  = K / 64;

    float acc[4][4][4];
#pragma unroll
    for (int mi = 0; mi < 4; ++mi)
#pragma unroll
        for (int ni = 0; ni < 4; ++ni)
#pragma unroll
            for (int r = 0; r < 4; ++r) acc[mi][ni][r] = 0.f;

    auto issue = [&](int kt, int s) {
        const unsigned sb = smBase + (unsigned)s * (HSTAGE * 2);
#pragma unroll
        for (int p = 0; p < 4; ++p) {       // A: 1024 chunks / 256 thr
            int idx = p * 256 + tid;
            int r = idx >> 3, c = idx & 7;
            CPA16(sb + (unsigned)(r * 128 + ((c ^ (r & 7)) * 16)),
                  A + (size_t)(row0 + r) * K + kt * 64 + c * 8);
        }
#pragma unroll
        for (int p = 0; p < 4; ++p) {       // B: 1024 chunks
            int idx = p * 256 + tid;
            int r = idx >> 3, c = idx & 7;
            CPA16(sb + 16384u + (unsigned)(r * 128 + ((c ^ (r & 7)) * 16)),
                  Bt + (size_t)(col0 + r) * K + kt * 64 + c * 8);
        }
        asm volatile("cp.async.commit_group;");
    };

    issue(0, 0);

    // ldmatrix lane decomposition (constant per thread)
    const int lr  = lane & 15;          // row-in-tile for A
    const int lc  = lane >> 4;          // chunk parity for A
    const int bn8 = 8 * (lane >> 4) + (lane & 7);   // B row offset within 16
    const int bcp = (lane >> 3) & 1;                // B chunk parity

    for (int kt = 0; kt < NKT; ++kt) {
        const int s = kt & 1;
        asm volatile("cp.async.wait_group 0;");   // group kt complete
        __syncthreads();                          // publish; prior readers of s^1 done
        if (kt + 1 < NKT) issue(kt + 1, s ^ 1);   // overlaps with compute below

        const unsigned sA = smBase + (unsigned)s * (HSTAGE * 2);
        const unsigned sB = sA + 16384u;

#pragma unroll
        for (int ks = 0; ks < 4; ++ks) {
            unsigned a[4][4];
#pragma unroll
            for (int mi = 0; mi < 4; ++mi) {
                int m = wm * 64 + mi * 16 + lr;
                int c = 2 * ks + lc;
                ldsm4(a[mi][0], a[mi][1], a[mi][2], a[mi][3],
                      sA + (unsigned)(2 * (m * 64 + ((c ^ (m & 7)) << 3))));
            }
            unsigned b[4][2];
#pragma unroll
            for (int blk = 0; blk < 2; ++blk) {
                int n = wn * 32 + 16 * blk + bn8;
                int c = 2 * ks + bcp;
                ldsm4(b[2 * blk][0], b[2 * blk][1], b[2 * blk + 1][0], b[2 * blk + 1][1],
                      sB + (unsigned)(2 * (n * 64 + ((c ^ (n & 7)) << 3))));
            }
#pragma unroll
            for (int mi = 0; mi < 4; ++mi)
#pragma unroll
                for (int ni = 0; ni < 4; ++ni)
                    mma_f16(acc[mi][ni], a[mi][0], a[mi][1], a[mi][2], a[mi][3],
                            b[ni][0], b[ni][1]);
        }
    }

    // epilogue
#pragma unroll
    for (int ni = 0; ni < 4; ++ni) {
        int col = col0 + wn * 32 + ni * 8 + 2 * tg;
        float bx = 0.f, by = 0.f;
        if (WITH_BIAS) { bx = bias[col]; by = bias[col + 1]; }
#pragma unroll
        for (int mi = 0; mi < 4; ++mi) {
            int row = row0 + wm * 64 + mi * 16 + g;
            if (HALF_OUT) {
                __half* C = (__half*)Cout;
                __half2 h0 = __floats2half2_rn(acc[mi][ni][0], acc[mi][ni][1]);
                __half2 h1 = __floats2half2_rn(acc[mi][ni][2], acc[mi][ni][3]);
                *reinterpret_cast<__half2*>(&C[(size_t)row * N + col]) = h0;
                *reinterpret_cast<__half2*>(&C[(size_t)(row + 8) * N + col]) = h1;
            } else {
                float* C = (float*)Cout;
                float2 v0 = make_float2(acc[mi][ni][0] + bx, acc[mi][ni][1] + by);
                float2 v1 = make_float2(acc[mi][ni][2] + bx, acc[mi][ni][3] + by);
                *reinterpret_cast<float2*>(&C[(size_t)row * N + col]) = v0;
                *reinterpret_cast<float2*>(&C[(size_t)(row + 8) * N + col]) = v1;
            }
        }
    }
}

// ---------------- FP16 tensor-core attention ----------------
// One CTA per (window, head), 256 threads (8 warps x 16 query rows).
// smem (halves), all "row r, chunk c at c^(r&7)" swizzled:
//   qs [128][64] @0, ks [256][64] @8192, vs [256][64] @24576.
// Q/K cp.async (group A), V cp.async (group B) overlapped under S+softmax.
// PV uses ldmatrix.x4.trans on row-major V.
#define ATTN_SMEM_B (40960 * 2)            // 81920 bytes

__global__ __launch_bounds__(256)
void attn_h16_kernel(const __half* __restrict__ qkv, __half* __restrict__ o)
{
    extern __shared__ __half hs[];
    const unsigned smB = (unsigned)__cvta_generic_to_shared(hs);
    const unsigned qsB = smB;
    const unsigned ksB = smB + 8192u * 2u;
    const unsigned vsB = smB + 24576u * 2u;

    const int w    = blockIdx.x;
    const int h    = blockIdx.y;
    const int tid  = threadIdx.x;
    const int lane = tid & 31;
    const int wq   = tid >> 5;
    const int g    = lane >> 2;
    const int tg   = lane & 3;
    const int m0   = wq * 16;
    const int tok0 = w * WSZ;

    // ---- group A: Q (1024 chunks) + K (2048 chunks) ----
#pragma unroll
    for (int p = 0; p < 4; ++p) {
        int idx = p * 256 + tid;
        int row = idx >> 3, c = idx & 7;
        CPA16(qsB + (unsigned)(row * 128 + ((c ^ (row & 7)) * 16)),
              qkv + (size_t)(tok0 + row) * QKVW + h * DHEAD + c * 8);
    }
#pragma unroll
    for (int p = 0; p < 8; ++p) {
        int idx = p * 256 + tid;
        int j = idx >> 3, c = idx & 7;
        const __half* src = (w == 0 && j < WSZ)
            ? g_zero16
            : qkv + (size_t)(tok0 - WSZ + j) * QKVW + HD + h * DHEAD + c * 8;
        CPA16(ksB + (unsigned)(j * 128 + ((c ^ (j & 7)) * 16)), src);
    }
    asm volatile("cp.async.commit_group;");

    // ---- group B: V (2048 chunks) ----
#pragma unroll
    for (int p = 0; p < 8; ++p) {
        int idx = p * 256 + tid;
        int j = idx >> 3, c = idx & 7;
        const __half* src = (w == 0 && j < WSZ)
            ? g_zero16
            : qkv + (size_t)(tok0 - WSZ + j) * QKVW + 2 * HD + h * DHEAD + c * 8;
        CPA16(vsB + (unsigned)(j * 128 + ((c ^ (j & 7)) * 16)), src);
    }
    asm volatile("cp.async.commit_group;");

    asm volatile("cp.async.wait_group 1;");   // Q + K ready
    __syncthreads();

    // ldmatrix lane decomposition
    const int lr  = lane & 15;
    const int lc  = lane >> 4;
    const int bn8 = 8 * (lane >> 4) + (lane & 7);
    const int bcp = (lane >> 3) & 1;
    const int rr   = lane & 7;            // trans-ldsm row within tile
    const int tsel = lane >> 3;           // trans-ldsm tile select 0..3

    // ---- Q A-fragments ----
    unsigned qa[4][4];
#pragma unroll
    for (int ks = 0; ks < 4; ++ks) {
        int m = m0 + lr;
        int c = 2 * ks + lc;
        ldsm4(qa[ks][0], qa[ks][1], qa[ks][2], qa[ks][3],
              qsB + (unsigned)(2 * (m * 64 + ((c ^ (m & 7)) << 3))));
    }

    // ---- S = Q @ K^T ----
    float s[32][4];
#pragma unroll
    for (int nt = 0; nt < 32; ++nt) {
        s[nt][0] = 0.f; s[nt][1] = 0.f; s[nt][2] = 0.f; s[nt][3] = 0.f;
    }
#pragma unroll
    for (int ntp = 0; ntp < 16; ++ntp) {
        const int jb = 16 * ntp + bn8;
#pragma unroll
        for (int ks = 0; ks < 4; ++ks) {
            int c = 2 * ks + bcp;
            unsigned b0, b1, b2, b3;
            ldsm4(b0, b1, b2, b3,
                  ksB + (unsigned)(2 * (jb * 64 + ((c ^ (jb & 7)) << 3))));
            mma_f16(s[2 * ntp],     qa[ks][0], qa[ks][1], qa[ks][2], qa[ks][3], b0, b1);
            mma_f16(s[2 * ntp + 1], qa[ks][0], qa[ks][1], qa[ks][2], qa[ks][3], b2, b3);
        }
    }

    // ---- scale (d^-1/2 = 0.125) + mask + softmax ----
    const int i_lo = m0 + g, i_hi = i_lo + 8;
    float mx0 = -3.0e38f, mx1 = -3.0e38f;
#pragma unroll
    for (int nt = 0; nt < 32; ++nt) {
        int j0 = 8 * nt + 2 * tg, j1 = j0 + 1;
        s[nt][0] = (j0 > i_lo + WSZ) ? -1e10f : s[nt][0] * 0.125f;
        s[nt][1] = (j1 > i_lo + WSZ) ? -1e10f : s[nt][1] * 0.125f;
        s[nt][2] = (j0 > i_hi + WSZ) ? -1e10f : s[nt][2] * 0.125f;
        s[nt][3] = (j1 > i_hi + WSZ) ? -1e10f : s[nt][3] * 0.125f;
        mx0 = fmaxf(mx0, fmaxf(s[nt][0], s[nt][1]));
        mx1 = fmaxf(mx1, fmaxf(s[nt][2], s[nt][3]));
    }
    mx0 = fmaxf(mx0, __shfl_xor_sync(0xffffffffu, mx0, 1));
    mx0 = fmaxf(mx0, __shfl_xor_sync(0xffffffffu, mx0, 2));
    mx1 = fmaxf(mx1, __shfl_xor_sync(0xffffffffu, mx1, 1));
    mx1 = fmaxf(mx1, __shfl_xor_sync(0xffffffffu, mx1, 2));

    float l0 = 0.f, l1 = 0.f;
    unsigned ph[32][2];
#pragma unroll
    for (int nt = 0; nt < 32; ++nt) {
        float p0 = __expf(s[nt][0] - mx0);
        float p1 = __expf(s[nt][1] - mx0);
        float p2 = __expf(s[nt][2] - mx1);
        float p3 = __expf(s[nt][3] - mx1);
        l0 += p0 + p1;
        l1 += p2 + p3;
        ph[nt][0] = h2u(__floats2half2_rn(p0, p1));
        ph[nt][1] = h2u(__floats2half2_rn(p2, p3));
    }
    l0 += __shfl_xor_sync(0xffffffffu, l0, 1);
    l0 += __shfl_xor_sync(0xffffffffu, l0, 2);
    l1 += __shfl_xor_sync(0xffffffffu, l1, 1);
    l1 += __shfl_xor_sync(0xffffffffu, l1, 2);

    asm volatile("cp.async.wait_group 0;");   // V ready (loaded under S+softmax)
    __syncthreads();

    // ---- O = P @ V : trans-ldmatrix B fragments straight from row-major V ----
    float ov[8][4];
#pragma unroll
    for (int nt = 0; nt < 8; ++nt) {
        ov[nt][0] = 0.f; ov[nt][1] = 0.f; ov[nt][2] = 0.f; ov[nt][3] = 0.f;
    }
#pragma unroll
    for (int kj = 0; kj < 16; ++kj) {
        unsigned a0 = ph[2 * kj][0];
        unsigned a1 = ph[2 * kj][1];
        unsigned a2 = ph[2 * kj + 1][0];
        unsigned a3 = ph[2 * kj + 1][1];
        const int row = 16 * kj + 8 * (tsel & 1) + rr;
#pragma unroll
        for (int ntp = 0; ntp < 4; ++ntp) {
            int ch = 2 * ntp + (tsel >> 1);
            unsigned b0, b1, b2, b3;
            ldsm4t(b0, b1, b2, b3,
                   vsB + (unsigned)(2 * (row * 64 + ((ch ^ (row & 7)) << 3))));
            mma_f16(ov[2 * ntp],     a0, a1, a2, a3, b0, b1);
            mma_f16(ov[2 * ntp + 1], a0, a1, a2, a3, b2, b3);
        }
    }

    // ---- normalize + write half ----
    float inv0 = 1.f / l0, inv1 = 1.f / l1;
    const int row_lo = tok0 + m0 + g;
#pragma unroll
    for (int nt = 0; nt < 8; ++nt) {
        int col = h * DHEAD + 8 * nt + 2 * tg;
        __half2 h0 = __floats2half2_rn(ov[nt][0] * inv0, ov[nt][1] * inv0);
        __half2 h1 = __floats2half2_rn(ov[nt][2] * inv1, ov[nt][3] * inv1);
        *reinterpret_cast<__half2*>(&o[(size_t)row_lo * HD + col]) = h0;
        *reinterpret_cast<__half2*>(&o[(size_t)(row_lo + 8) * HD + col]) = h1;
    }
}

// ---------------- launch ----------------
extern "C" void kernel_launch(void* const* d_in, const int* in_sizes, int n_in,
                              void* d_out, int out_size)
{
    (void)in_sizes; (void)n_in; (void)out_size;
    const float* x     = (const float*)d_in[0];  // [16384, 1024]
    const float* w_qkv = (const float*)d_in[1];  // [1024, 1536]
    const float* w_out = (const float*)d_in[2];  // [512, 1024]
    const float* b_out = (const float*)d_in[3];  // [1024]
    float*       out   = (float*)d_out;          // [16384, 1024]

    __half *xh, *wqkvT, *woutT, *qkvh, *attnh;
    cudaGetSymbolAddress((void**)&xh,    g_xh);
    cudaGetSymbolAddress((void**)&wqkvT, g_wqkvT);
    cudaGetSymbolAddress((void**)&woutT, g_woutT);
    cudaGetSymbolAddress((void**)&qkvh,  g_qkvh);
    cudaGetSymbolAddress((void**)&attnh, g_attnh);

    cudaFuncSetAttribute((const void*)h16gemm<false, true>,
                         cudaFuncAttributeMaxDynamicSharedMemorySize, HG_SMEM);
    cudaFuncSetAttribute((const void*)h16gemm<true, false>,
                         cudaFuncAttributeMaxDynamicSharedMemorySize, HG_SMEM);
    cudaFuncSetAttribute((const void*)attn_h16_kernel,
                         cudaFuncAttributeMaxDynamicSharedMemorySize, ATTN_SMEM_B);

    // 0) convert x -> half; transpose+convert weights -> half
    {
        int n4 = N_TOK * DIM / 4;
        cvt_f2h<<<(n4 + 255) / 256, 256>>>((const float4*)x, (__half2*)xh, n4);
        transpose_f2h<<<dim3(QKVW / 32, DIM / 32), dim3(32, 8)>>>(w_qkv, wqkvT, DIM, QKVW);
        transpose_f2h<<<dim3(DIM / 32, HD / 32),  dim3(32, 8)>>>(w_out, woutT, HD, DIM);
    }

    // 1) QKV projection: [16384,1024] @ [1024,1536], half out
    {
        dim3 grid(QKVW / 128, N_TOK / 128);
        h16gemm<false, true><<<grid, 256, HG_SMEM>>>(xh, wqkvT, nullptr, qkvh,
                                                     N_TOK, QKVW, DIM);
    }

    // 2) windowed look-back attention (fp16 mma, fp32 softmax)
    {
        dim3 grid(NWIN, HEADS);
        attn_h16_kernel<<<grid, 256, ATTN_SMEM_B>>>(qkvh, attnh);
    }

    // 3) output projection: [16384,512] @ [512,1024] + bias, fp32 out
    {
        dim3 grid(DIM / 128, N_TOK / 128);
        h16gemm<true, false><<<grid, 256, HG_SMEM>>>(attnh, woutT, b_out, out,
                                                     N_TOK, DIM, HD);
    }
}

// round 13
// speedup vs baseline: 1.4571x; 1.4571x over previous
#include <cuda_runtime.h>
#include <cuda_fp16.h>
#include <cstdint>

// ---------------- problem constants ----------------
#define N_TOK   16384
#define DIM     1024
#define HEADS   8
#define DHEAD   64
#define HD      (HEADS * DHEAD)   // 512
#define QKVW    (3 * HD)          // 1536
#define WSZ     128
#define NWIN    (N_TOK / WSZ)     // 128

// ---------------- scratch ----------------
__device__ __half g_xh[(size_t)N_TOK * DIM];      // x -> half
__device__ __half g_wqkvT[(size_t)QKVW * DIM];    // w_qkv^T half  [1536][1024]
__device__ __half g_woutT[(size_t)DIM * HD];      // w_out^T half  [1024][512]
__device__ __half g_qkvh[(size_t)N_TOK * QKVW];   // GEMM1 out half
__device__ __half g_attnh[(size_t)N_TOK * HD];    // attention out half
__device__ __align__(16) __half g_zero16[8];      // 16B of zeros, 16B-aligned (cp.async src)

// ---------------- helpers ----------------
__device__ __forceinline__ unsigned h2u(__half2 h) {
    return *reinterpret_cast<unsigned*>(&h);
}

__device__ __forceinline__ void mma_f16(float c[4], unsigned a0, unsigned a1,
                                        unsigned a2, unsigned a3,
                                        unsigned b0, unsigned b1) {
    asm volatile(
        "mma.sync.aligned.m16n8k16.row.col.f32.f16.f16.f32 "
        "{%0,%1,%2,%3}, {%4,%5,%6,%7}, {%8,%9}, {%0,%1,%2,%3};"
        : "+f"(c[0]), "+f"(c[1]), "+f"(c[2]), "+f"(c[3])
        : "r"(a0), "r"(a1), "r"(a2), "r"(a3), "r"(b0), "r"(b1));
}

__device__ __forceinline__ void ldsm4(unsigned& r0, unsigned& r1,
                                      unsigned& r2, unsigned& r3, unsigned addr) {
    asm volatile("ldmatrix.sync.aligned.m8n8.x4.shared.b16 {%0,%1,%2,%3}, [%4];"
                 : "=r"(r0), "=r"(r1), "=r"(r2), "=r"(r3) : "r"(addr));
}

__device__ __forceinline__ void ldsm4t(unsigned& r0, unsigned& r1,
                                       unsigned& r2, unsigned& r3, unsigned addr) {
    asm volatile("ldmatrix.sync.aligned.m8n8.x4.trans.shared.b16 {%0,%1,%2,%3}, [%4];"
                 : "=r"(r0), "=r"(r1), "=r"(r2), "=r"(r3) : "r"(addr));
}

__global__ void cvt_f2h(const float4* __restrict__ in,
                        __half2* __restrict__ out, int n4)
{
    int i = blockIdx.x * blockDim.x + threadIdx.x;
    if (i < n4) {
        float4 v = in[i];
        out[2 * i + 0] = __floats2half2_rn(v.x, v.y);
        out[2 * i + 1] = __floats2half2_rn(v.z, v.w);
    }
}

// in[R][C] fp32 -> out[C][R] half. block (32,8), grid (C/32, R/32).
__global__ void transpose_f2h(const float* __restrict__ in,
                              __half* __restrict__ out, int R, int C)
{
    __shared__ float t[32][33];
    int bx = blockIdx.x * 32, by = blockIdx.y * 32;
    int x = bx + threadIdx.x;
#pragma unroll
    for (int i = 0; i < 32; i += 8) {
        int y = by + threadIdx.y + i;
        t[threadIdx.y + i][threadIdx.x] = in[(size_t)y * C + x];
    }
    __syncthreads();
    int xo = by + threadIdx.x;
#pragma unroll
    for (int i = 0; i < 32; i += 8) {
        int yo = bx + threadIdx.y + i;
        out[(size_t)yo * R + xo] = __float2half_rn(t[threadIdx.x][threadIdx.y + i]);
    }
}

// ---------------- FP16 tensor-core GEMM (round-8 proven 3-stage schedule) ----------------
// C[M,N] = A[M,K] @ Bt[N,K]^T (+bias). A, Bt half row-major.
// CTA 128x128x64(halves), 8 warps 2x4 (warp tile 64x32),
// 3-stage cp.async pipeline (wait_group 1, prefetch distance 2),
// ldmatrix.x4 fragment loads. smem row r = 64 halves, 16B chunk c at c^(r&7).
// Stage s at byte offset s*32768; A [0,16384), B [16384,32768) within stage.
#define CPA16(dst, src) \
    asm volatile("cp.async.cg.shared.global [%0], [%1], 16;" :: "r"(dst), "l"(src))

#define HSTAGE 16384                       // halves per stage (A 8192 + B 8192)
#define HG_SMEM (3 * HSTAGE * 2)           // 98304 bytes

template <bool WITH_BIAS, bool HALF_OUT>
__global__ __launch_bounds__(256, 2)
void h16gemm(const __half* __restrict__ A, const __half* __restrict__ Bt,
             const float* __restrict__ bias, void* __restrict__ Cout,
             int M, int N, int K)
{
    extern __shared__ __half hsm[];
    const unsigned smBase = (unsigned)__cvta_generic_to_shared(hsm);

    const int tid  = threadIdx.x;
    const int lane = tid & 31;
    const int wid  = tid >> 5;
    const int wm   = wid >> 2;          // 0..1
    const int wn   = wid & 3;           // 0..3
    const int g    = lane >> 2;         // 0..7
    const int tg   = lane & 3;          // 0..3

    const int row0 = blockIdx.y * 128;
    const int col0 = blockIdx.x * 128;
    const int NKT  = K / 64;

    float acc[4][4][4];
#pragma unroll
    for (int mi = 0; mi < 4; ++mi)
#pragma unroll
        for (int ni = 0; ni < 4; ++ni)
#pragma unroll
            for (int r = 0; r < 4; ++r) acc[mi][ni][r] = 0.f;

    auto issue = [&](int kt, int s) {
        const unsigned sb = smBase + (unsigned)s * (HSTAGE * 2);
#pragma unroll
        for (int p = 0; p < 4; ++p) {       // A: 1024 chunks / 256 thr
            int idx = p * 256 + tid;
            int r = idx >> 3, c = idx & 7;
            CPA16(sb + (unsigned)(r * 128 + ((c ^ (r & 7)) * 16)),
                  A + (size_t)(row0 + r) * K + kt * 64 + c * 8);
        }
#pragma unroll
        for (int p = 0; p < 4; ++p) {       // B: 1024 chunks
            int idx = p * 256 + tid;
            int r = idx >> 3, c = idx & 7;
            CPA16(sb + 16384u + (unsigned)(r * 128 + ((c ^ (r & 7)) * 16)),
                  Bt + (size_t)(col0 + r) * K + kt * 64 + c * 8);
        }
        asm volatile("cp.async.commit_group;");
    };

    issue(0, 0);
    issue(1, 1);

    // ldmatrix lane decomposition (constant per thread)
    const int lr  = lane & 15;          // row-in-tile for A
    const int lc  = lane >> 4;          // chunk parity for A
    const int bn8 = 8 * (lane >> 4) + (lane & 7);   // B row offset within 16
    const int bcp = (lane >> 3) & 1;                // B chunk parity

    for (int kt = 0; kt < NKT; ++kt) {
        const int s = kt % 3;
        if (kt + 1 < NKT) asm volatile("cp.async.wait_group 1;");
        else              asm volatile("cp.async.wait_group 0;");
        __syncthreads();
        if (kt + 2 < NKT) issue(kt + 2, (kt + 2) % 3);

        const unsigned sA = smBase + (unsigned)s * (HSTAGE * 2);
        const unsigned sB = sA + 16384u;

#pragma unroll
        for (int ks = 0; ks < 4; ++ks) {
            unsigned a[4][4];
#pragma unroll
            for (int mi = 0; mi < 4; ++mi) {
                int m = wm * 64 + mi * 16 + lr;
                int c = 2 * ks + lc;
                ldsm4(a[mi][0], a[mi][1], a[mi][2], a[mi][3],
                      sA + (unsigned)(2 * (m * 64 + ((c ^ (m & 7)) << 3))));
            }
            unsigned b[4][2];
#pragma unroll
            for (int blk = 0; blk < 2; ++blk) {
                int n = wn * 32 + 16 * blk + bn8;
                int c = 2 * ks + bcp;
                ldsm4(b[2 * blk][0], b[2 * blk][1], b[2 * blk + 1][0], b[2 * blk + 1][1],
                      sB + (unsigned)(2 * (n * 64 + ((c ^ (n & 7)) << 3))));
            }
#pragma unroll
            for (int mi = 0; mi < 4; ++mi)
#pragma unroll
                for (int ni = 0; ni < 4; ++ni)
                    mma_f16(acc[mi][ni], a[mi][0], a[mi][1], a[mi][2], a[mi][3],
                            b[ni][0], b[ni][1]);
        }
        __syncthreads();
    }

    // epilogue
#pragma unroll
    for (int ni = 0; ni < 4; ++ni) {
        int col = col0 + wn * 32 + ni * 8 + 2 * tg;
        float bx = 0.f, by = 0.f;
        if (WITH_BIAS) { bx = bias[col]; by = bias[col + 1]; }
#pragma unroll
        for (int mi = 0; mi < 4; ++mi) {
            int row = row0 + wm * 64 + mi * 16 + g;
            if (HALF_OUT) {
                __half* C = (__half*)Cout;
                __half2 h0 = __floats2half2_rn(acc[mi][ni][0], acc[mi][ni][1]);
                __half2 h1 = __floats2half2_rn(acc[mi][ni][2], acc[mi][ni][3]);
                *reinterpret_cast<__half2*>(&C[(size_t)row * N + col]) = h0;
                *reinterpret_cast<__half2*>(&C[(size_t)(row + 8) * N + col]) = h1;
            } else {
                float* C = (float*)Cout;
                float2 v0 = make_float2(acc[mi][ni][0] + bx, acc[mi][ni][1] + by);
                float2 v1 = make_float2(acc[mi][ni][2] + bx, acc[mi][ni][3] + by);
                *reinterpret_cast<float2*>(&C[(size_t)row * N + col]) = v0;
                *reinterpret_cast<float2*>(&C[(size_t)(row + 8) * N + col]) = v1;
            }
        }
    }
}

// ---------------- FP16 tensor-core attention (round-12, passed) ----------------
// One CTA per (window, head), 256 threads (8 warps x 16 query rows).
// smem (halves), all "row r, chunk c at c^(r&7)" swizzled:
//   qs [128][64] @0, ks [256][64] @8192, vs [256][64] @24576.
// Q/K cp.async (group A), V cp.async (group B) overlapped under S+softmax.
// PV uses ldmatrix.x4.trans on row-major V.
#define ATTN_SMEM_B (40960 * 2)            // 81920 bytes

__global__ __launch_bounds__(256)
void attn_h16_kernel(const __half* __restrict__ qkv, __half* __restrict__ o)
{
    extern __shared__ __half hs[];
    const unsigned smB = (unsigned)__cvta_generic_to_shared(hs);
    const unsigned qsB = smB;
    const unsigned ksB = smB + 8192u * 2u;
    const unsigned vsB = smB + 24576u * 2u;

    const int w    = blockIdx.x;
    const int h    = blockIdx.y;
    const int tid  = threadIdx.x;
    const int lane = tid & 31;
    const int wq   = tid >> 5;
    const int g    = lane >> 2;
    const int tg   = lane & 3;
    const int m0   = wq * 16;
    const int tok0 = w * WSZ;

    // ---- group A: Q (1024 chunks) + K (2048 chunks) ----
#pragma unroll
    for (int p = 0; p < 4; ++p) {
        int idx = p * 256 + tid;
        int row = idx >> 3, c = idx & 7;
        CPA16(qsB + (unsigned)(row * 128 + ((c ^ (row & 7)) * 16)),
              qkv + (size_t)(tok0 + row) * QKVW + h * DHEAD + c * 8);
    }
#pragma unroll
    for (int p = 0; p < 8; ++p) {
        int idx = p * 256 + tid;
        int j = idx >> 3, c = idx & 7;
        const __half* src = (w == 0 && j < WSZ)
            ? g_zero16
            : qkv + (size_t)(tok0 - WSZ + j) * QKVW + HD + h * DHEAD + c * 8;
        CPA16(ksB + (unsigned)(j * 128 + ((c ^ (j & 7)) * 16)), src);
    }
    asm volatile("cp.async.commit_group;");

    // ---- group B: V (2048 chunks) ----
#pragma unroll
    for (int p = 0; p < 8; ++p) {
        int idx = p * 256 + tid;
        int j = idx >> 3, c = idx & 7;
        const __half* src = (w == 0 && j < WSZ)
            ? g_zero16
            : qkv + (size_t)(tok0 - WSZ + j) * QKVW + 2 * HD + h * DHEAD + c * 8;
        CPA16(vsB + (unsigned)(j * 128 + ((c ^ (j & 7)) * 16)), src);
    }
    asm volatile("cp.async.commit_group;");

    asm volatile("cp.async.wait_group 1;");   // Q + K ready
    __syncthreads();

    // ldmatrix lane decomposition
    const int lr  = lane & 15;
    const int lc  = lane >> 4;
    const int bn8 = 8 * (lane >> 4) + (lane & 7);
    const int bcp = (lane >> 3) & 1;
    const int rr   = lane & 7;            // trans-ldsm row within tile
    const int tsel = lane >> 3;           // trans-ldsm tile select 0..3

    // ---- Q A-fragments ----
    unsigned qa[4][4];
#pragma unroll
    for (int ks = 0; ks < 4; ++ks) {
        int m = m0 + lr;
        int c = 2 * ks + lc;
        ldsm4(qa[ks][0], qa[ks][1], qa[ks][2], qa[ks][3],
              qsB + (unsigned)(2 * (m * 64 + ((c ^ (m & 7)) << 3))));
    }

    // ---- S = Q @ K^T ----
    float s[32][4];
#pragma unroll
    for (int nt = 0; nt < 32; ++nt) {
        s[nt][0] = 0.f; s[nt][1] = 0.f; s[nt][2] = 0.f; s[nt][3] = 0.f;
    }
#pragma unroll
    for (int ntp = 0; ntp < 16; ++ntp) {
        const int jb = 16 * ntp + bn8;
#pragma unroll
        for (int ks = 0; ks < 4; ++ks) {
            int c = 2 * ks + bcp;
            unsigned b0, b1, b2, b3;
            ldsm4(b0, b1, b2, b3,
                  ksB + (unsigned)(2 * (jb * 64 + ((c ^ (jb & 7)) << 3))));
            mma_f16(s[2 * ntp],     qa[ks][0], qa[ks][1], qa[ks][2], qa[ks][3], b0, b1);
            mma_f16(s[2 * ntp + 1], qa[ks][0], qa[ks][1], qa[ks][2], qa[ks][3], b2, b3);
        }
    }

    // ---- scale (d^-1/2 = 0.125) + mask + softmax ----
    const int i_lo = m0 + g, i_hi = i_lo + 8;
    float mx0 = -3.0e38f, mx1 = -3.0e38f;
#pragma unroll
    for (int nt = 0; nt < 32; ++nt) {
        int j0 = 8 * nt + 2 * tg, j1 = j0 + 1;
        s[nt][0] = (j0 > i_lo + WSZ) ? -1e10f : s[nt][0] * 0.125f;
        s[nt][1] = (j1 > i_lo + WSZ) ? -1e10f : s[nt][1] * 0.125f;
        s[nt][2] = (j0 > i_hi + WSZ) ? -1e10f : s[nt][2] * 0.125f;
        s[nt][3] = (j1 > i_hi + WSZ) ? -1e10f : s[nt][3] * 0.125f;
        mx0 = fmaxf(mx0, fmaxf(s[nt][0], s[nt][1]));
        mx1 = fmaxf(mx1, fmaxf(s[nt][2], s[nt][3]));
    }
    mx0 = fmaxf(mx0, __shfl_xor_sync(0xffffffffu, mx0, 1));
    mx0 = fmaxf(mx0, __shfl_xor_sync(0xffffffffu, mx0, 2));
    mx1 = fmaxf(mx1, __shfl_xor_sync(0xffffffffu, mx1, 1));
    mx1 = fmaxf(mx1, __shfl_xor_sync(0xffffffffu, mx1, 2));

    float l0 = 0.f, l1 = 0.f;
    unsigned ph[32][2];
#pragma unroll
    for (int nt = 0; nt < 32; ++nt) {
        float p0 = __expf(s[nt][0] - mx0);
        float p1 = __expf(s[nt][1] - mx0);
        float p2 = __expf(s[nt][2] - mx1);
        float p3 = __expf(s[nt][3] - mx1);
        l0 += p0 + p1;
        l1 += p2 + p3;
        ph[nt][0] = h2u(__floats2half2_rn(p0, p1));
        ph[nt][1] = h2u(__floats2half2_rn(p2, p3));
    }
    l0 += __shfl_xor_sync(0xffffffffu, l0, 1);
    l0 += __shfl_xor_sync(0xffffffffu, l0, 2);
    l1 += __shfl_xor_sync(0xffffffffu, l1, 1);
    l1 += __shfl_xor_sync(0xffffffffu, l1, 2);

    asm volatile("cp.async.wait_group 0;");   // V ready (loaded under S+softmax)
    __syncthreads();

    // ---- O = P @ V : trans-ldmatrix B fragments straight from row-major V ----
    float ov[8][4];
#pragma unroll
    for (int nt = 0; nt < 8; ++nt) {
        ov[nt][0] = 0.f; ov[nt][1] = 0.f; ov[nt][2] = 0.f; ov[nt][3] = 0.f;
    }
#pragma unroll
    for (int kj = 0; kj < 16; ++kj) {
        unsigned a0 = ph[2 * kj][0];
        unsigned a1 = ph[2 * kj][1];
        unsigned a2 = ph[2 * kj + 1][0];
        unsigned a3 = ph[2 * kj + 1][1];
        const int row = 16 * kj + 8 * (tsel & 1) + rr;
#pragma unroll
        for (int ntp = 0; ntp < 4; ++ntp) {
            int ch = 2 * ntp + (tsel >> 1);
            unsigned b0, b1, b2, b3;
            ldsm4t(b0, b1, b2, b3,
                   vsB + (unsigned)(2 * (row * 64 + ((ch ^ (row & 7)) << 3))));
            mma_f16(ov[2 * ntp],     a0, a1, a2, a3, b0, b1);
            mma_f16(ov[2 * ntp + 1], a0, a1, a2, a3, b2, b3);
        }
    }

    // ---- normalize + write half ----
    float inv0 = 1.f / l0, inv1 = 1.f / l1;
    const int row_lo = tok0 + m0 + g;
#pragma unroll
    for (int nt = 0; nt < 8; ++nt) {
        int col = h * DHEAD + 8 * nt + 2 * tg;
        __half2 h0 = __floats2half2_rn(ov[nt][0] * inv0, ov[nt][1] * inv0);
        __half2 h1 = __floats2half2_rn(ov[nt][2] * inv1, ov[nt][3] * inv1);
        *reinterpret_cast<__half2*>(&o[(size_t)row_lo * HD + col]) = h0;
        *reinterpret_cast<__half2*>(&o[(size_t)(row_lo + 8) * HD + col]) = h1;
    }
}

// ---------------- launch ----------------
extern "C" void kernel_launch(void* const* d_in, const int* in_sizes, int n_in,
                              void* d_out, int out_size)
{
    (void)in_sizes; (void)n_in; (void)out_size;
    const float* x     = (const float*)d_in[0];  // [16384, 1024]
    const float* w_qkv = (const float*)d_in[1];  // [1024, 1536]
    const float* w_out = (const float*)d_in[2];  // [512, 1024]
    const float* b_out = (const float*)d_in[3];  // [1024]
    float*       out   = (float*)d_out;          // [16384, 1024]

    __half *xh, *wqkvT, *woutT, *qkvh, *attnh;
    cudaGetSymbolAddress((void**)&xh,    g_xh);
    cudaGetSymbolAddress((void**)&wqkvT, g_wqkvT);
    cudaGetSymbolAddress((void**)&woutT, g_woutT);
    cudaGetSymbolAddress((void**)&qkvh,  g_qkvh);
    cudaGetSymbolAddress((void**)&attnh, g_attnh);

    cudaFuncSetAttribute((const void*)h16gemm<false, true>,
                         cudaFuncAttributeMaxDynamicSharedMemorySize, HG_SMEM);
    cudaFuncSetAttribute((const void*)h16gemm<true, false>,
                         cudaFuncAttributeMaxDynamicSharedMemorySize, HG_SMEM);
    cudaFuncSetAttribute((const void*)attn_h16_kernel,
                         cudaFuncAttributeMaxDynamicSharedMemorySize, ATTN_SMEM_B);

    // 0) convert x -> half; transpose+convert weights -> half
    {
        int n4 = N_TOK * DIM / 4;
        cvt_f2h<<<(n4 + 255) / 256, 256>>>((const float4*)x, (__half2*)xh, n4);
        transpose_f2h<<<dim3(QKVW / 32, DIM / 32), dim3(32, 8)>>>(w_qkv, wqkvT, DIM, QKVW);
        transpose_f2h<<<dim3(DIM / 32, HD / 32),  dim3(32, 8)>>>(w_out, woutT, HD, DIM);
    }

    // 1) QKV projection: [16384,1024] @ [1024,1536], half out
    {
        dim3 grid(QKVW / 128, N_TOK / 128);
        h16gemm<false, true><<<grid, 256, HG_SMEM>>>(xh, wqkvT, nullptr, qkvh,
                                                     N_TOK, QKVW, DIM);
    }

    // 2) windowed look-back attention (fp16 mma, fp32 softmax)
    {
        dim3 grid(NWIN, HEADS);
        attn_h16_kernel<<<grid, 256, ATTN_SMEM_B>>>(qkvh, attnh);
    }

    // 3) output projection: [16384,512] @ [512,1024] + bias, fp32 out
    {
        dim3 grid(DIM / 128, N_TOK / 128);
        h16gemm<true, false><<<grid, 256, HG_SMEM>>>(attnh, woutT, b_out, out,
                                                     N_TOK, DIM, HD);
    }
}